// round 6
// baseline (speedup 1.0000x reference)
#include <cuda_runtime.h>

// ---------------------------------------------------------------------------
// BinaryAssociativeMemory on GB300 — round 2 (byte-identical resubmit; rounds
// 1-2 failed at container acquisition with no harness output; round 0 proved
// containers run the harness fine. Clean infra-vs-kernel discrimination.)
//
// Pipeline (all graph-capturable, default stream, no allocations):
//  1) proj_qkv : q = (x@Wq^T)*SCALE ; k = sign(x@Wk^T) ; v = sign(x@Wv^T)
//  2) chunk_delta : Sc[b,h,c] = kc^T @ vc   (exact ±1 products)
//  3) prefix_state : exclusive prefix over chunks -> states; final -> d_out tail
//  4) chunk_scores : tril(qc @ kc^T)
//  5) chunk_out : outpre = scores@vc + qc@state[c]
//  6) proj_o : out = outpre @ Wo^T -> d_out head
// ---------------------------------------------------------------------------

#define Bsz 4
#define Tsz 4096
#define Dsz 2048
#define Hsz 16
#define DH  128
#define CH  128
#define NC  32
#define Msz (Bsz*Tsz)   // 16384
#define BH  (Bsz*Hsz)   // 64

// Scratch (static __device__ arrays; rewritten fully every launch)
__device__ float g_q[33554432];       // [16384, 2048]
__device__ float g_k[33554432];
__device__ float g_v[33554432];
__device__ float g_pre[33554432];     // pre-Wo output
__device__ float g_scores[33554432];  // [64*32][128][128]
__device__ float g_states[34603008];  // [64][33][128][128] (slot c = exclusive prefix)

// -------------------- generic 128x128 tile, 8x8 microtile ------------------
// threads: 256 ; tx = tid&15 (cols), ty = tid>>4 (rows)

#define INNER_STEP(kk)                                                        \
    {                                                                         \
        float a[8], b[8];                                                     \
        *reinterpret_cast<float4*>(a)   = *reinterpret_cast<const float4*>(&As[kk][ty*8]);   \
        *reinterpret_cast<float4*>(a+4) = *reinterpret_cast<const float4*>(&As[kk][ty*8+4]); \
        *reinterpret_cast<float4*>(b)   = *reinterpret_cast<const float4*>(&Bs[kk][tx*8]);   \
        *reinterpret_cast<float4*>(b+4) = *reinterpret_cast<const float4*>(&Bs[kk][tx*8+4]); \
        _Pragma("unroll")                                                     \
        for (int u = 0; u < 8; u++)                                           \
            _Pragma("unroll")                                                 \
            for (int v = 0; v < 8; v++)                                       \
                acc[u][v] += a[u] * b[v];                                     \
    }

// -------------------- 1) fused QKV projection (TN sgemm) -------------------
__global__ __launch_bounds__(256) void proj_qkv_kernel(
    const float* __restrict__ x, const float* __restrict__ Wq,
    const float* __restrict__ Wk, const float* __restrict__ Wv)
{
    const int n0 = blockIdx.x * 128;
    const int m0 = blockIdx.y * 128;
    const int mode = blockIdx.z;                 // 0=q, 1=k, 2=v
    const float* __restrict__ W = (mode == 0) ? Wq : ((mode == 1) ? Wk : Wv);
    float* __restrict__ out = (mode == 0) ? g_q : ((mode == 1) ? g_k : g_v);

    __shared__ float As[16][132];
    __shared__ float Bs[16][132];
    float acc[8][8];
#pragma unroll
    for (int u = 0; u < 8; u++)
#pragma unroll
        for (int v = 0; v < 8; v++) acc[u][v] = 0.f;

    const int tid = threadIdx.x;
    const int tx = tid & 15, ty = tid >> 4;

    for (int k0 = 0; k0 < 2048; k0 += 16) {
#pragma unroll
        for (int r = 0; r < 2; r++) {
            int linear = r * 256 + tid;          // 0..511
            int mm = linear >> 2;                // row within tile
            int kq = (linear & 3) << 2;          // k sub-offset
            float4 va = *reinterpret_cast<const float4*>(x + (size_t)(m0 + mm) * 2048 + k0 + kq);
            As[kq + 0][mm] = va.x; As[kq + 1][mm] = va.y; As[kq + 2][mm] = va.z; As[kq + 3][mm] = va.w;
            float4 vb = *reinterpret_cast<const float4*>(W + (size_t)(n0 + mm) * 2048 + k0 + kq);
            Bs[kq + 0][mm] = vb.x; Bs[kq + 1][mm] = vb.y; Bs[kq + 2][mm] = vb.z; Bs[kq + 3][mm] = vb.w;
        }
        __syncthreads();
#pragma unroll
        for (int kk = 0; kk < 16; kk++) INNER_STEP(kk);
        __syncthreads();
    }

    const float SCALE = 0.08838834764831845f;    // 1/sqrt(128)
#pragma unroll
    for (int u = 0; u < 8; u++) {
        int row = m0 + ty * 8 + u;
#pragma unroll
        for (int v = 0; v < 8; v++) {
            int col = n0 + tx * 8 + v;
            float val = acc[u][v];
            if (mode == 0)       val *= SCALE;
            else                 val = (val >= 0.f) ? 1.f : -1.f;
            out[(size_t)row * 2048 + col] = val;
        }
    }
}

// -------------------- 2) per-chunk outer product Sc = kc^T @ vc ------------
__global__ __launch_bounds__(256) void chunk_delta_kernel()
{
    const int c = blockIdx.x;                    // 0..31
    const int bh = blockIdx.y;                   // 0..63
    const int b = bh >> 4, h = bh & 15;
    const size_t base_row = (size_t)b * 4096 + (size_t)c * 128;
    const int col0 = h * 128;

    __shared__ float As[16][132];
    __shared__ float Bs[16][132];
    float acc[8][8];
#pragma unroll
    for (int u = 0; u < 8; u++)
#pragma unroll
        for (int v = 0; v < 8; v++) acc[u][v] = 0.f;

    const int tid = threadIdx.x;
    const int tx = tid & 15, ty = tid >> 4;

    for (int t0 = 0; t0 < 128; t0 += 16) {
#pragma unroll
        for (int r = 0; r < 2; r++) {
            int linear = r * 256 + tid;
            int kk = linear >> 5;                // 0..15 (token within subtile)
            int i4 = (linear & 31) << 2;         // col within head
            *reinterpret_cast<float4*>(&As[kk][i4]) =
                *reinterpret_cast<const float4*>(g_k + (base_row + t0 + kk) * 2048 + col0 + i4);
            *reinterpret_cast<float4*>(&Bs[kk][i4]) =
                *reinterpret_cast<const float4*>(g_v + (base_row + t0 + kk) * 2048 + col0 + i4);
        }
        __syncthreads();
#pragma unroll
        for (int kk = 0; kk < 16; kk++) INNER_STEP(kk);
        __syncthreads();
    }

    float* dst = g_states + ((size_t)bh * 33 + c + 1) * 16384;
#pragma unroll
    for (int u = 0; u < 8; u++)
#pragma unroll
        for (int v = 0; v < 8; v++)
            dst[(ty * 8 + u) * 128 + tx * 8 + v] = acc[u][v];
}

// -------------------- 3) exclusive prefix of states; emit final state ------
__global__ __launch_bounds__(256) void prefix_state_kernel(float* __restrict__ out_state)
{
    int idx = blockIdx.x * 256 + threadIdx.x;    // < 64*16384
    int bh = idx >> 14;
    int rest = idx & 16383;
    size_t base = (size_t)bh * 33 * 16384 + rest;
    g_states[base] = 0.f;                        // slot 0 = exclusive prefix for chunk 0
    float run = 0.f;
#pragma unroll
    for (int c = 0; c < 32; c++) {
        size_t p = base + (size_t)(c + 1) * 16384;
        run += g_states[p];                      // exact integer adds
        g_states[p] = run;                       // slot c+1 = exclusive prefix for chunk c+1
    }
    out_state[idx] = run;                        // final_state [b,h,i,j]
}

// -------------------- 4) masked intra-chunk scores -------------------------
__global__ __launch_bounds__(256) void chunk_scores_kernel()
{
    const int c = blockIdx.x;
    const int bh = blockIdx.y;
    const int b = bh >> 4, h = bh & 15;
    const size_t base_row = (size_t)b * 4096 + (size_t)c * 128;
    const int col0 = h * 128;

    __shared__ float As[16][132];
    __shared__ float Bs[16][132];
    float acc[8][8];
#pragma unroll
    for (int u = 0; u < 8; u++)
#pragma unroll
        for (int v = 0; v < 8; v++) acc[u][v] = 0.f;

    const int tid = threadIdx.x;
    const int tx = tid & 15, ty = tid >> 4;

    for (int k0 = 0; k0 < 128; k0 += 16) {
#pragma unroll
        for (int r = 0; r < 2; r++) {
            int linear = r * 256 + tid;
            int mm = linear >> 2;
            int kq = (linear & 3) << 2;
            float4 va = *reinterpret_cast<const float4*>(g_q + (base_row + mm) * 2048 + col0 + k0 + kq);
            As[kq + 0][mm] = va.x; As[kq + 1][mm] = va.y; As[kq + 2][mm] = va.z; As[kq + 3][mm] = va.w;
            float4 vb = *reinterpret_cast<const float4*>(g_k + (base_row + mm) * 2048 + col0 + k0 + kq);
            Bs[kq + 0][mm] = vb.x; Bs[kq + 1][mm] = vb.y; Bs[kq + 2][mm] = vb.z; Bs[kq + 3][mm] = vb.w;
        }
        __syncthreads();
#pragma unroll
        for (int kk = 0; kk < 16; kk++) INNER_STEP(kk);
        __syncthreads();
    }

    float* dst = g_scores + ((size_t)bh * 32 + c) * 16384;
#pragma unroll
    for (int u = 0; u < 8; u++) {
        int row = ty * 8 + u;
#pragma unroll
        for (int v = 0; v < 8; v++) {
            int col = tx * 8 + v;
            dst[row * 128 + col] = (col <= row) ? acc[u][v] : 0.f;  // tril mask
        }
    }
}

// -------------------- 5) outpre = scores@vc + qc@state[c] ------------------
__global__ __launch_bounds__(256) void chunk_out_kernel()
{
    const int c = blockIdx.x;
    const int bh = blockIdx.y;
    const int b = bh >> 4, h = bh & 15;
    const size_t base_row = (size_t)b * 4096 + (size_t)c * 128;
    const int col0 = h * 128;

    __shared__ float As[16][132];
    __shared__ float Bs[16][132];
    float acc[8][8];
#pragma unroll
    for (int u = 0; u < 8; u++)
#pragma unroll
        for (int v = 0; v < 8; v++) acc[u][v] = 0.f;

    const int tid = threadIdx.x;
    const int tx = tid & 15, ty = tid >> 4;

    const float* sc = g_scores + ((size_t)bh * 32 + c) * 16384;

    // part 1: intra = scores @ vc   (A row-major [i][t], B = v rows)
    for (int t0 = 0; t0 < 128; t0 += 16) {
#pragma unroll
        for (int r = 0; r < 2; r++) {
            int linear = r * 256 + tid;
            int mm = linear >> 2;
            int kq = (linear & 3) << 2;
            float4 va = *reinterpret_cast<const float4*>(sc + mm * 128 + t0 + kq);
            As[kq + 0][mm] = va.x; As[kq + 1][mm] = va.y; As[kq + 2][mm] = va.z; As[kq + 3][mm] = va.w;
            int kk = linear >> 5;
            int e4 = (linear & 31) << 2;
            *reinterpret_cast<float4*>(&Bs[kk][e4]) =
                *reinterpret_cast<const float4*>(g_v + (base_row + t0 + kk) * 2048 + col0 + e4);
        }
        __syncthreads();
#pragma unroll
        for (int kk = 0; kk < 16; kk++) INNER_STEP(kk);
        __syncthreads();
    }

    // part 2: cross = qc @ state[c]  (state slot c = exclusive prefix)
    const float* st = g_states + ((size_t)bh * 33 + c) * 16384;
    for (int j0 = 0; j0 < 128; j0 += 16) {
#pragma unroll
        for (int r = 0; r < 2; r++) {
            int linear = r * 256 + tid;
            int mm = linear >> 2;
            int kq = (linear & 3) << 2;
            float4 va = *reinterpret_cast<const float4*>(g_q + (base_row + mm) * 2048 + col0 + j0 + kq);
            As[kq + 0][mm] = va.x; As[kq + 1][mm] = va.y; As[kq + 2][mm] = va.z; As[kq + 3][mm] = va.w;
            int kk = linear >> 5;
            int e4 = (linear & 31) << 2;
            *reinterpret_cast<float4*>(&Bs[kk][e4]) =
                *reinterpret_cast<const float4*>(st + (j0 + kk) * 128 + e4);
        }
        __syncthreads();
#pragma unroll
        for (int kk = 0; kk < 16; kk++) INNER_STEP(kk);
        __syncthreads();
    }

#pragma unroll
    for (int u = 0; u < 8; u++)
#pragma unroll
        for (int v = 0; v < 8; v++)
            g_pre[(base_row + ty * 8 + u) * 2048 + col0 + tx * 8 + v] = acc[u][v];
}

// -------------------- 6) output projection (TN sgemm) ----------------------
__global__ __launch_bounds__(256) void proj_o_kernel(const float* __restrict__ Wo,
                                                     float* __restrict__ out)
{
    const int n0 = blockIdx.x * 128;
    const int m0 = blockIdx.y * 128;

    __shared__ float As[16][132];
    __shared__ float Bs[16][132];
    float acc[8][8];
#pragma unroll
    for (int u = 0; u < 8; u++)
#pragma unroll
        for (int v = 0; v < 8; v++) acc[u][v] = 0.f;

    const int tid = threadIdx.x;
    const int tx = tid & 15, ty = tid >> 4;

    for (int k0 = 0; k0 < 2048; k0 += 16) {
#pragma unroll
        for (int r = 0; r < 2; r++) {
            int linear = r * 256 + tid;
            int mm = linear >> 2;
            int kq = (linear & 3) << 2;
            float4 va = *reinterpret_cast<const float4*>(g_pre + (size_t)(m0 + mm) * 2048 + k0 + kq);
            As[kq + 0][mm] = va.x; As[kq + 1][mm] = va.y; As[kq + 2][mm] = va.z; As[kq + 3][mm] = va.w;
            float4 vb = *reinterpret_cast<const float4*>(Wo + (size_t)(n0 + mm) * 2048 + k0 + kq);
            Bs[kq + 0][mm] = vb.x; Bs[kq + 1][mm] = vb.y; Bs[kq + 2][mm] = vb.z; Bs[kq + 3][mm] = vb.w;
        }
        __syncthreads();
#pragma unroll
        for (int kk = 0; kk < 16; kk++) INNER_STEP(kk);
        __syncthreads();
    }

#pragma unroll
    for (int u = 0; u < 8; u++) {
        int row = m0 + ty * 8 + u;
#pragma unroll
        for (int v = 0; v < 8; v++) {
            int col = n0 + tx * 8 + v;
            out[(size_t)row * 2048 + col] = acc[u][v];
        }
    }
}

// ---------------------------------------------------------------------------
extern "C" void kernel_launch(void* const* d_in, const int* in_sizes, int n_in,
                              void* d_out, int out_size)
{
    const float* x  = (const float*)d_in[0];
    const float* Wq = (const float*)d_in[1];
    const float* Wk = (const float*)d_in[2];
    const float* Wv = (const float*)d_in[3];
    const float* Wo = (const float*)d_in[4];
    float* out = (float*)d_out;                 // [33554432] out + [1048576] final_state

    proj_qkv_kernel<<<dim3(16, 128, 3), 256>>>(x, Wq, Wk, Wv);
    chunk_delta_kernel<<<dim3(32, 64), 256>>>();
    prefix_state_kernel<<<4096, 256>>>(out + 33554432);
    chunk_scores_kernel<<<dim3(32, 64), 256>>>();
    chunk_out_kernel<<<dim3(32, 64), 256>>>();
    proj_o_kernel<<<dim3(16, 128), 256>>>(Wo, out);
}

// round 12
// speedup vs baseline: 1.0093x; 1.0093x over previous
#include <cuda_runtime.h>
#include <cuda_fp16.h>
#include <cstdint>

// ---------------------------------------------------------------------------
// BinaryAssociativeMemory on GB300 — round 12.
// R11 passed numerically except K/V sign flips from HMMA's non-IEEE fp32
// accumulation (~5e-6 deviation vs fp32). Fix: collect K/V elements with
// |y| < 1e-3 during the HMMA epilogue and recompute their signs exactly in
// fp32 (warp-per-candidate fixup). Q/O keep raw HMMA (not thresholded).
// All global scratch resolved in DEVICE code (R10 host-shadow bug).
// ---------------------------------------------------------------------------

#define FIX_CAP 8388608

// ------------------------------- scratch ----------------------------------
__device__ float g_q[33554432];       // [16384, 2048]
__device__ float g_k[33554432];
__device__ float g_v[33554432];
__device__ float g_pre[33554432];
__device__ float g_scores[33554432];  // [64*32][128][128]
__device__ float g_states[34603008];  // [64][33][128][128]
__device__ __half g_xh[33554432], g_xl[33554432];   // x fp16 splits
__device__ __half g_ph[33554432], g_pl[33554432];   // pre fp16 splits
__device__ __half g_wh[16777216], g_wl[16777216];   // Wq|Wk|Wv|Wo splits
__device__ int g_cnt[2];
__device__ unsigned g_cand[2][FIX_CAP];

#define MMA16816(d, a, b) \
    asm volatile("mma.sync.aligned.m16n8k16.row.col.f32.f16.f16.f32 " \
                 "{%0,%1,%2,%3}, {%4,%5,%6,%7}, {%8,%9}, {%0,%1,%2,%3};" \
                 : "+f"((d)[0]), "+f"((d)[1]), "+f"((d)[2]), "+f"((d)[3]) \
                 : "r"((a)[0]), "r"((a)[1]), "r"((a)[2]), "r"((a)[3]), \
                   "r"((b)[0]), "r"((b)[1]))

// --------------------------- reset kernel -----------------------------------
__global__ void reset_cnt_kernel() {
    if (threadIdx.x < 2) g_cnt[threadIdx.x] = 0;
}

// --------------------------- fp16 split kernel ------------------------------
// hi = fp16(x); lo = fp16((x - hi) * 2048)
// sel: 0 -> x; 1..4 -> W (Wq,Wk,Wv,Wo); 5 -> g_pre
__global__ __launch_bounds__(256) void split_h_kernel(
    const float* __restrict__ src_ext, int sel, int n4)
{
    const float* src;
    __half* hi;
    __half* lo;
    if (sel == 0)      { src = src_ext; hi = g_xh; lo = g_xl; }
    else if (sel <= 4) {
        size_t off = (size_t)(sel - 1) * 4194304;
        src = src_ext; hi = g_wh + off; lo = g_wl + off;
    } else             { src = g_pre;  hi = g_ph; lo = g_pl; }

    int i = blockIdx.x * 256 + threadIdx.x;
    int stride = gridDim.x * 256;
    for (; i < n4; i += stride) {
        float4 v = reinterpret_cast<const float4*>(src)[i];
        __half h0 = __float2half_rn(v.x);
        __half h1 = __float2half_rn(v.y);
        __half h2 = __float2half_rn(v.z);
        __half h3 = __float2half_rn(v.w);
        __half l0 = __float2half_rn((v.x - __half2float(h0)) * 2048.0f);
        __half l1 = __float2half_rn((v.y - __half2float(h1)) * 2048.0f);
        __half l2 = __float2half_rn((v.z - __half2float(h2)) * 2048.0f);
        __half l3 = __float2half_rn((v.w - __half2float(h3)) * 2048.0f);
        __half2* hp = reinterpret_cast<__half2*>(hi + (size_t)i * 4);
        __half2* lp = reinterpret_cast<__half2*>(lo + (size_t)i * 4);
        hp[0] = __halves2half2(h0, h1); hp[1] = __halves2half2(h2, h3);
        lp[0] = __halves2half2(l0, l1); lp[1] = __halves2half2(l2, l3);
    }
}

// --------------------- fp16 3-term HMMA GEMM --------------------------------
// C[16384,2048] = A @ B^T (TN). CTA 128x64x32, 8 warps, warp 32x32.
// sel: 0 -> q (*SCALE), 1 -> k (sign+fixup), 2 -> v (sign+fixup), 3 -> out
__global__ __launch_bounds__(256) void hgemm3_kernel(float* __restrict__ dst_ext, int sel)
{
    const __half* Ah;
    const __half* Al;
    const __half* Bh;
    const __half* Bl;
    float* dst;
    int mode;
    if (sel < 3) {
        Ah = g_xh; Al = g_xl;
        size_t off = (size_t)sel * 4194304;
        Bh = g_wh + off; Bl = g_wl + off;
        dst = (sel == 0) ? g_q : ((sel == 1) ? g_k : g_v);
        mode = (sel == 0) ? 0 : 1;
    } else {
        Ah = g_ph; Al = g_pl;
        Bh = g_wh + 12582912; Bl = g_wl + 12582912;
        dst = dst_ext;
        mode = 2;
    }
    const int cidx = sel - 1;   // valid when mode==1

    __shared__ __align__(16) __half sAh[128][40];
    __shared__ __align__(16) __half sAl[128][40];
    __shared__ __align__(16) __half sBh[64][40];
    __shared__ __align__(16) __half sBl[64][40];

    const int tid = threadIdx.x;
    const int wid = tid >> 5, lid = tid & 31;
    const int wm = wid & 3, wn2 = wid >> 2;
    const int n0 = blockIdx.x * 64, m0 = blockIdx.y * 128;
    const int gid = lid >> 2, t4 = lid & 3;

    float acc1[2][4][4], acc2[2][4][4];
#pragma unroll
    for (int mt = 0; mt < 2; mt++)
#pragma unroll
        for (int nt = 0; nt < 4; nt++)
#pragma unroll
            for (int e = 0; e < 4; e++) { acc1[mt][nt][e] = 0.f; acc2[mt][nt][e] = 0.f; }

    uint4 ra[4], rb[2];

#define LOAD_REGS(k0)                                                              \
    {                                                                              \
        _Pragma("unroll")                                                          \
        for (int q = 0; q < 4; q++) {                                              \
            int ch = q * 256 + tid;                                                \
            int s = ch >> 9, rem = ch & 511, row = rem >> 2, c = rem & 3;          \
            const __half* src = (s ? Al : Ah) + (size_t)(m0 + row) * 2048 + (k0) + c * 8; \
            ra[q] = *reinterpret_cast<const uint4*>(src);                          \
        }                                                                          \
        _Pragma("unroll")                                                          \
        for (int q = 0; q < 2; q++) {                                              \
            int ch = q * 256 + tid;                                                \
            int s = ch >> 8, rem = ch & 255, row = rem >> 2, c = rem & 3;          \
            const __half* src = (s ? Bl : Bh) + (size_t)(n0 + row) * 2048 + (k0) + c * 8; \
            rb[q] = *reinterpret_cast<const uint4*>(src);                          \
        }                                                                          \
    }

#define STORE_REGS()                                                               \
    {                                                                              \
        _Pragma("unroll")                                                          \
        for (int q = 0; q < 4; q++) {                                              \
            int ch = q * 256 + tid;                                                \
            int s = ch >> 9, rem = ch & 511, row = rem >> 2, c = rem & 3;          \
            __half* d = (s ? &sAl[0][0] : &sAh[0][0]) + row * 40 + c * 8;          \
            *reinterpret_cast<uint4*>(d) = ra[q];                                  \
        }                                                                          \
        _Pragma("unroll")                                                          \
        for (int q = 0; q < 2; q++) {                                              \
            int ch = q * 256 + tid;                                                \
            int s = ch >> 8, rem = ch & 255, row = rem >> 2, c = rem & 3;          \
            __half* d = (s ? &sBl[0][0] : &sBh[0][0]) + row * 40 + c * 8;          \
            *reinterpret_cast<uint4*>(d) = rb[q];                                  \
        }                                                                          \
    }

    LOAD_REGS(0);

    for (int it = 0; it < 64; it++) {
        __syncthreads();
        STORE_REGS();
        __syncthreads();
        if (it + 1 < 64) LOAD_REGS((it + 1) * 32);

#pragma unroll
        for (int ks = 0; ks < 2; ks++) {
            const int kb = ks * 16 + t4 * 2;
            uint32_t afh[2][4], afl[2][4], bfh[4][2], bfl[4][2];
#pragma unroll
            for (int mt = 0; mt < 2; mt++) {
                int r = wm * 32 + mt * 16 + gid;
                afh[mt][0] = *reinterpret_cast<const uint32_t*>(&sAh[r][kb]);
                afh[mt][1] = *reinterpret_cast<const uint32_t*>(&sAh[r + 8][kb]);
                afh[mt][2] = *reinterpret_cast<const uint32_t*>(&sAh[r][kb + 8]);
                afh[mt][3] = *reinterpret_cast<const uint32_t*>(&sAh[r + 8][kb + 8]);
                afl[mt][0] = *reinterpret_cast<const uint32_t*>(&sAl[r][kb]);
                afl[mt][1] = *reinterpret_cast<const uint32_t*>(&sAl[r + 8][kb]);
                afl[mt][2] = *reinterpret_cast<const uint32_t*>(&sAl[r][kb + 8]);
                afl[mt][3] = *reinterpret_cast<const uint32_t*>(&sAl[r + 8][kb + 8]);
            }
#pragma unroll
            for (int nt = 0; nt < 4; nt++) {
                int r = wn2 * 32 + nt * 8 + gid;
                bfh[nt][0] = *reinterpret_cast<const uint32_t*>(&sBh[r][kb]);
                bfh[nt][1] = *reinterpret_cast<const uint32_t*>(&sBh[r][kb + 8]);
                bfl[nt][0] = *reinterpret_cast<const uint32_t*>(&sBl[r][kb]);
                bfl[nt][1] = *reinterpret_cast<const uint32_t*>(&sBl[r][kb + 8]);
            }
#pragma unroll
            for (int mt = 0; mt < 2; mt++)
#pragma unroll
                for (int nt = 0; nt < 4; nt++) {
                    MMA16816(acc1[mt][nt], afh[mt], bfh[nt]);
                    MMA16816(acc2[mt][nt], afh[mt], bfl[nt]);
                    MMA16816(acc2[mt][nt], afl[mt], bfh[nt]);
                }
        }
    }

    const float INV = 4.8828125e-4f;          // 2^-11
    const float SCALE = 0.08838834764831845f; // 1/sqrt(128)
    const float TAU = 1e-3f;                  // fixup threshold (~200 sigma)
#pragma unroll
    for (int mt = 0; mt < 2; mt++)
#pragma unroll
        for (int nt = 0; nt < 4; nt++) {
            int row = m0 + wm * 32 + mt * 16 + gid;
            int col = n0 + wn2 * 32 + nt * 8 + t4 * 2;
            float d0 = acc1[mt][nt][0] + acc2[mt][nt][0] * INV;
            float d1 = acc1[mt][nt][1] + acc2[mt][nt][1] * INV;
            float d2 = acc1[mt][nt][2] + acc2[mt][nt][2] * INV;
            float d3 = acc1[mt][nt][3] + acc2[mt][nt][3] * INV;
            if (mode == 0) { d0 *= SCALE; d1 *= SCALE; d2 *= SCALE; d3 *= SCALE; }
            else if (mode == 1) {
                unsigned base0 = (unsigned)(row * 2048 + col);
                unsigned base2 = base0 + 8 * 2048;
                if (fabsf(d0) < TAU) { int ix = atomicAdd(&g_cnt[cidx], 1); if (ix < FIX_CAP) g_cand[cidx][ix] = base0; }
                if (fabsf(d1) < TAU) { int ix = atomicAdd(&g_cnt[cidx], 1); if (ix < FIX_CAP) g_cand[cidx][ix] = base0 + 1; }
                if (fabsf(d2) < TAU) { int ix = atomicAdd(&g_cnt[cidx], 1); if (ix < FIX_CAP) g_cand[cidx][ix] = base2; }
                if (fabsf(d3) < TAU) { int ix = atomicAdd(&g_cnt[cidx], 1); if (ix < FIX_CAP) g_cand[cidx][ix] = base2 + 1; }
                d0 = (d0 >= 0.f) ? 1.f : -1.f; d1 = (d1 >= 0.f) ? 1.f : -1.f;
                d2 = (d2 >= 0.f) ? 1.f : -1.f; d3 = (d3 >= 0.f) ? 1.f : -1.f;
            }
            *reinterpret_cast<float2*>(dst + (size_t)row * 2048 + col) = make_float2(d0, d1);
            *reinterpret_cast<float2*>(dst + (size_t)(row + 8) * 2048 + col) = make_float2(d2, d3);
        }
}

// --------------------- exact-sign fixup (warp per candidate) ----------------
__global__ __launch_bounds__(256) void fixup_kernel(
    const float* __restrict__ x, const float* __restrict__ W, int which)
{
    int cnt = g_cnt[which];
    if (cnt > FIX_CAP) cnt = FIX_CAP;
    int wgid = (blockIdx.x * 256 + threadIdx.x) >> 5;
    int lane = threadIdx.x & 31;
    int nw = (gridDim.x * 256) >> 5;
    float* dst = which ? g_v : g_k;
    const unsigned* cand = g_cand[which];
    for (int i = wgid; i < cnt; i += nw) {
        unsigned pc = cand[i];
        int row = pc >> 11, col = pc & 2047;
        const float4* xr = reinterpret_cast<const float4*>(x + (size_t)row * 2048);
        const float4* wr = reinterpret_cast<const float4*>(W + (size_t)col * 2048);
        float s = 0.f;
        for (int j = lane; j < 512; j += 32) {
            float4 a = xr[j], b = wr[j];
            s += a.x * b.x + a.y * b.y + a.z * b.z + a.w * b.w;
        }
#pragma unroll
        for (int o = 16; o; o >>= 1) s += __shfl_xor_sync(0xFFFFFFFFu, s, o);
        if (lane == 0) dst[(size_t)row * 2048 + col] = (s >= 0.f) ? 1.f : -1.f;
    }
}

// ------------------ chunk kernels (unchanged from passing run) --------------
#define INNER_STEP(kk)                                                        \
    {                                                                         \
        float a[8], b[8];                                                     \
        *reinterpret_cast<float4*>(a)   = *reinterpret_cast<const float4*>(&As[kk][ty*8]);   \
        *reinterpret_cast<float4*>(a+4) = *reinterpret_cast<const float4*>(&As[kk][ty*8+4]); \
        *reinterpret_cast<float4*>(b)   = *reinterpret_cast<const float4*>(&Bs[kk][tx*8]);   \
        *reinterpret_cast<float4*>(b+4) = *reinterpret_cast<const float4*>(&Bs[kk][tx*8+4]); \
        _Pragma("unroll")                                                     \
        for (int u = 0; u < 8; u++)                                           \
            _Pragma("unroll")                                                 \
            for (int v = 0; v < 8; v++)                                       \
                acc[u][v] += a[u] * b[v];                                     \
    }

__global__ __launch_bounds__(256) void chunk_delta_kernel()
{
    const int c = blockIdx.x;
    const int bh = blockIdx.y;
    const int b = bh >> 4, h = bh & 15;
    const size_t base_row = (size_t)b * 4096 + (size_t)c * 128;
    const int col0 = h * 128;

    __shared__ float As[16][132];
    __shared__ float Bs[16][132];
    float acc[8][8];
#pragma unroll
    for (int u = 0; u < 8; u++)
#pragma unroll
        for (int v = 0; v < 8; v++) acc[u][v] = 0.f;

    const int tid = threadIdx.x;
    const int tx = tid & 15, ty = tid >> 4;

    for (int t0 = 0; t0 < 128; t0 += 16) {
#pragma unroll
        for (int r = 0; r < 2; r++) {
            int linear = r * 256 + tid;
            int kk = linear >> 5;
            int i4 = (linear & 31) << 2;
            *reinterpret_cast<float4*>(&As[kk][i4]) =
                *reinterpret_cast<const float4*>(g_k + (base_row + t0 + kk) * 2048 + col0 + i4);
            *reinterpret_cast<float4*>(&Bs[kk][i4]) =
                *reinterpret_cast<const float4*>(g_v + (base_row + t0 + kk) * 2048 + col0 + i4);
        }
        __syncthreads();
#pragma unroll
        for (int kk = 0; kk < 16; kk++) INNER_STEP(kk);
        __syncthreads();
    }

    float* dst = g_states + ((size_t)bh * 33 + c + 1) * 16384;
#pragma unroll
    for (int u = 0; u < 8; u++)
#pragma unroll
        for (int v = 0; v < 8; v++)
            dst[(ty * 8 + u) * 128 + tx * 8 + v] = acc[u][v];
}

__global__ __launch_bounds__(256) void prefix_state_kernel(float* __restrict__ out_state)
{
    int idx = blockIdx.x * 256 + threadIdx.x;
    int bh = idx >> 14;
    int rest = idx & 16383;
    size_t base = (size_t)bh * 33 * 16384 + rest;
    g_states[base] = 0.f;
    float run = 0.f;
#pragma unroll
    for (int c = 0; c < 32; c++) {
        size_t p = base + (size_t)(c + 1) * 16384;
        run += g_states[p];
        g_states[p] = run;
    }
    out_state[idx] = run;
}

__global__ __launch_bounds__(256) void chunk_scores_kernel()
{
    const int c = blockIdx.x;
    const int bh = blockIdx.y;
    const int b = bh >> 4, h = bh & 15;
    const size_t base_row = (size_t)b * 4096 + (size_t)c * 128;
    const int col0 = h * 128;

    __shared__ float As[16][132];
    __shared__ float Bs[16][132];
    float acc[8][8];
#pragma unroll
    for (int u = 0; u < 8; u++)
#pragma unroll
        for (int v = 0; v < 8; v++) acc[u][v] = 0.f;

    const int tid = threadIdx.x;
    const int tx = tid & 15, ty = tid >> 4;

    for (int k0 = 0; k0 < 128; k0 += 16) {
#pragma unroll
        for (int r = 0; r < 2; r++) {
            int linear = r * 256 + tid;
            int mm = linear >> 2;
            int kq = (linear & 3) << 2;
            float4 va = *reinterpret_cast<const float4*>(g_q + (base_row + mm) * 2048 + col0 + k0 + kq);
            As[kq + 0][mm] = va.x; As[kq + 1][mm] = va.y; As[kq + 2][mm] = va.z; As[kq + 3][mm] = va.w;
            float4 vb = *reinterpret_cast<const float4*>(g_k + (base_row + mm) * 2048 + col0 + k0 + kq);
            Bs[kq + 0][mm] = vb.x; Bs[kq + 1][mm] = vb.y; Bs[kq + 2][mm] = vb.z; Bs[kq + 3][mm] = vb.w;
        }
        __syncthreads();
#pragma unroll
        for (int kk = 0; kk < 16; kk++) INNER_STEP(kk);
        __syncthreads();
    }

    float* dst = g_scores + ((size_t)bh * 32 + c) * 16384;
#pragma unroll
    for (int u = 0; u < 8; u++) {
        int row = ty * 8 + u;
#pragma unroll
        for (int v = 0; v < 8; v++) {
            int col = tx * 8 + v;
            dst[row * 128 + col] = (col <= row) ? acc[u][v] : 0.f;
        }
    }
}

__global__ __launch_bounds__(256) void chunk_out_kernel()
{
    const int c = blockIdx.x;
    const int bh = blockIdx.y;
    const int b = bh >> 4, h = bh & 15;
    const size_t base_row = (size_t)b * 4096 + (size_t)c * 128;
    const int col0 = h * 128;

    __shared__ float As[16][132];
    __shared__ float Bs[16][132];
    float acc[8][8];
#pragma unroll
    for (int u = 0; u < 8; u++)
#pragma unroll
        for (int v = 0; v < 8; v++) acc[u][v] = 0.f;

    const int tid = threadIdx.x;
    const int tx = tid & 15, ty = tid >> 4;

    const float* sc = g_scores + ((size_t)bh * 32 + c) * 16384;

    for (int t0 = 0; t0 < 128; t0 += 16) {
#pragma unroll
        for (int r = 0; r < 2; r++) {
            int linear = r * 256 + tid;
            int mm = linear >> 2;
            int kq = (linear & 3) << 2;
            float4 va = *reinterpret_cast<const float4*>(sc + mm * 128 + t0 + kq);
            As[kq + 0][mm] = va.x; As[kq + 1][mm] = va.y; As[kq + 2][mm] = va.z; As[kq + 3][mm] = va.w;
            int kk = linear >> 5;
            int e4 = (linear & 31) << 2;
            *reinterpret_cast<float4*>(&Bs[kk][e4]) =
                *reinterpret_cast<const float4*>(g_v + (base_row + t0 + kk) * 2048 + col0 + e4);
        }
        __syncthreads();
#pragma unroll
        for (int kk = 0; kk < 16; kk++) INNER_STEP(kk);
        __syncthreads();
    }

    const float* st = g_states + ((size_t)bh * 33 + c) * 16384;
    for (int j0 = 0; j0 < 128; j0 += 16) {
#pragma unroll
        for (int r = 0; r < 2; r++) {
            int linear = r * 256 + tid;
            int mm = linear >> 2;
            int kq = (linear & 3) << 2;
            float4 va = *reinterpret_cast<const float4*>(g_q + (base_row + mm) * 2048 + col0 + j0 + kq);
            As[kq + 0][mm] = va.x; As[kq + 1][mm] = va.y; As[kq + 2][mm] = va.z; As[kq + 3][mm] = va.w;
            int kk = linear >> 5;
            int e4 = (linear & 31) << 2;
            *reinterpret_cast<float4*>(&Bs[kk][e4]) =
                *reinterpret_cast<const float4*>(st + (j0 + kk) * 128 + e4);
        }
        __syncthreads();
#pragma unroll
        for (int kk = 0; kk < 16; kk++) INNER_STEP(kk);
        __syncthreads();
    }

#pragma unroll
    for (int u = 0; u < 8; u++)
#pragma unroll
        for (int v = 0; v < 8; v++)
            g_pre[(base_row + ty * 8 + u) * 2048 + col0 + tx * 8 + v] = acc[u][v];
}

// ---------------------------------------------------------------------------
extern "C" void kernel_launch(void* const* d_in, const int* in_sizes, int n_in,
                              void* d_out, int out_size)
{
    const float* x  = (const float*)d_in[0];
    const float* Wq = (const float*)d_in[1];
    const float* Wk = (const float*)d_in[2];
    const float* Wv = (const float*)d_in[3];
    const float* Wo = (const float*)d_in[4];
    float* out = (float*)d_out;   // [33554432] out + [1048576] final_state

    reset_cnt_kernel<<<1, 32>>>();

    // fp16 hi/lo splits
    split_h_kernel<<<2048, 256>>>(x,  0, 8388608);
    split_h_kernel<<<1024, 256>>>(Wq, 1, 1048576);
    split_h_kernel<<<1024, 256>>>(Wk, 2, 1048576);
    split_h_kernel<<<1024, 256>>>(Wv, 3, 1048576);
    split_h_kernel<<<1024, 256>>>(Wo, 4, 1048576);

    // projections on HMMA (3-term fp16)
    hgemm3_kernel<<<dim3(32, 128), 256>>>(nullptr, 0);   // q
    hgemm3_kernel<<<dim3(32, 128), 256>>>(nullptr, 1);   // k
    hgemm3_kernel<<<dim3(32, 128), 256>>>(nullptr, 2);   // v

    // exact fp32 sign fixup for near-zero K/V projections
    fixup_kernel<<<1024, 256>>>(x, Wk, 0);
    fixup_kernel<<<1024, 256>>>(x, Wv, 1);

    // chunked recurrence (unchanged)
    chunk_delta_kernel<<<dim3(32, 64), 256>>>();
    prefix_state_kernel<<<4096, 256>>>(out + 33554432);
    chunk_scores_kernel<<<dim3(32, 64), 256>>>();
    chunk_out_kernel<<<dim3(32, 64), 256>>>();

    // output projection
    split_h_kernel<<<2048, 256>>>(nullptr, 5, 8388608);
    hgemm3_kernel<<<dim3(32, 128), 256>>>(out, 3);
}

// round 14
// speedup vs baseline: 1.7278x; 1.7118x over previous
#include <cuda_runtime.h>
#include <cuda_fp16.h>
#include <cstdint>

// ---------------------------------------------------------------------------
// BinaryAssociativeMemory on GB300 — round 14 (byte-identical resubmit of
// round 13; container-acquisition flake, same signature as R1/R2 which later
// ran verbatim. All mechanisms herein are proven on this toolchain: R9 ran
// cp.async+ldmatrix+dynamic-smem to completion; R12 passed with the same
// pipeline structure.)
// ---------------------------------------------------------------------------

#define FIX_CAP 8388608

// ------------------------------- scratch ----------------------------------
__device__ float g_q[33554432];       // [16384, 2048]
__device__ float g_k[33554432];
__device__ float g_v[33554432];
__device__ float g_pre[33554432];
__device__ float g_scores[33554432];  // [64*32][128][128]
__device__ float g_states[34603008];  // [64][33][128][128]
__device__ __half g_xh[33554432], g_xl[33554432];
__device__ __half g_ph[33554432], g_pl[33554432];
__device__ __half g_wh[16777216], g_wl[16777216];   // Wq|Wk|Wv|Wo
__device__ int g_cnt[2];
__device__ unsigned g_cand[2][FIX_CAP];

// --------------------------- asm helpers -----------------------------------
__device__ __forceinline__ uint32_t smem_u32(const void* p) {
    uint32_t a;
    asm("{ .reg .u64 t; cvta.to.shared.u64 t, %1; cvt.u32.u64 %0, t; }"
        : "=r"(a) : "l"(p));
    return a;
}

#define CP16(dst, src) \
    asm volatile("cp.async.cg.shared.global [%0], [%1], 16;" \
                 :: "r"(dst), "l"(src) : "memory")
#define CP_COMMIT() asm volatile("cp.async.commit_group;" ::: "memory")
#define CP_WAIT0()  asm volatile("cp.async.wait_group 0;" ::: "memory")

#define LDSM_X4(r, a) \
    asm volatile("ldmatrix.sync.aligned.m8n8.x4.shared.b16 {%0,%1,%2,%3}, [%4];" \
                 : "=r"((r)[0]), "=r"((r)[1]), "=r"((r)[2]), "=r"((r)[3]) : "r"(a))

#define MMA16816(d, a, b) \
    asm volatile("mma.sync.aligned.m16n8k16.row.col.f32.f16.f16.f32 " \
                 "{%0,%1,%2,%3}, {%4,%5,%6,%7}, {%8,%9}, {%0,%1,%2,%3};" \
                 : "+f"((d)[0]), "+f"((d)[1]), "+f"((d)[2]), "+f"((d)[3]) \
                 : "r"((a)[0]), "r"((a)[1]), "r"((a)[2]), "r"((a)[3]), \
                   "r"((b)[0]), "r"((b)[1]))

// --------------------------- reset kernel -----------------------------------
__global__ void reset_cnt_kernel() {
    if (threadIdx.x < 2) g_cnt[threadIdx.x] = 0;
}

// --------------------------- fp16 split kernel ------------------------------
// hi = fp16(x); lo = fp16((x - hi) * 2048)
// sel: 0 -> x; 1..4 -> W (Wq,Wk,Wv,Wo); 5 -> g_pre
__global__ __launch_bounds__(256) void split_h_kernel(
    const float* __restrict__ src_ext, int sel, int n4)
{
    const float* src;
    __half* hi;
    __half* lo;
    if (sel == 0)      { src = src_ext; hi = g_xh; lo = g_xl; }
    else if (sel <= 4) {
        size_t off = (size_t)(sel - 1) * 4194304;
        src = src_ext; hi = g_wh + off; lo = g_wl + off;
    } else             { src = g_pre;  hi = g_ph; lo = g_pl; }

    int i = blockIdx.x * 256 + threadIdx.x;
    int stride = gridDim.x * 256;
    for (; i < n4; i += stride) {
        float4 v = reinterpret_cast<const float4*>(src)[i];
        __half h0 = __float2half_rn(v.x);
        __half h1 = __float2half_rn(v.y);
        __half h2 = __float2half_rn(v.z);
        __half h3 = __float2half_rn(v.w);
        __half l0 = __float2half_rn((v.x - __half2float(h0)) * 2048.0f);
        __half l1 = __float2half_rn((v.y - __half2float(h1)) * 2048.0f);
        __half l2 = __float2half_rn((v.z - __half2float(h2)) * 2048.0f);
        __half l3 = __float2half_rn((v.w - __half2float(h3)) * 2048.0f);
        __half2* hp = reinterpret_cast<__half2*>(hi + (size_t)i * 4);
        __half2* lp = reinterpret_cast<__half2*>(lo + (size_t)i * 4);
        hp[0] = __halves2half2(h0, h1); hp[1] = __halves2half2(h2, h3);
        lp[0] = __halves2half2(l0, l1); lp[1] = __halves2half2(l2, l3);
    }
}

// --------------------- fp16 3-term HMMA GEMM (pipelined) --------------------
// C[16384,2048] = A @ B^T (TN). CTA 128x64x32, 8 warps, warp 32x32.
// cp.async double-buffered, ldmatrix fragments, 80B smem pitch.
// sel: 0 -> q (*SCALE), 1 -> k (sign+cand), 2 -> v (sign+cand), 3 -> out
#define OFF_AH 0
#define OFF_AL 10240
#define OFF_BH 20480
#define OFF_BL 25600
#define STAGE_BYTES 30720
#define SMEM_HG (2 * STAGE_BYTES)

__device__ __forceinline__ void ld_stage(
    uint32_t base, const __half* __restrict__ Ah, const __half* __restrict__ Al,
    const __half* __restrict__ Bh, const __half* __restrict__ Bl,
    int m0, int n0, int k0, int tid)
{
#pragma unroll
    for (int i = 0; i < 2; i++) {                       // A: 128 rows x 4x16B
        int ch = i * 256 + tid;
        int r = ch >> 2, c = ch & 3;
        uint32_t d = base + OFF_AH + r * 80 + c * 16;
        CP16(d, Ah + (size_t)(m0 + r) * 2048 + k0 + c * 8);
        d = base + OFF_AL + r * 80 + c * 16;
        CP16(d, Al + (size_t)(m0 + r) * 2048 + k0 + c * 8);
    }
    {                                                   // B: 64 rows x 4x16B
        int r = tid >> 2, c = tid & 3;
        uint32_t d = base + OFF_BH + r * 80 + c * 16;
        CP16(d, Bh + (size_t)(n0 + r) * 2048 + k0 + c * 8);
        d = base + OFF_BL + r * 80 + c * 16;
        CP16(d, Bl + (size_t)(n0 + r) * 2048 + k0 + c * 8);
    }
}

__global__ __launch_bounds__(256) void hgemm3_kernel(float* __restrict__ dst_ext, int sel)
{
    const __half* Ah;
    const __half* Al;
    const __half* Bh;
    const __half* Bl;
    float* dst;
    int mode;
    if (sel < 3) {
        Ah = g_xh; Al = g_xl;
        size_t off = (size_t)sel * 4194304;
        Bh = g_wh + off; Bl = g_wl + off;
        dst = (sel == 0) ? g_q : ((sel == 1) ? g_k : g_v);
        mode = (sel == 0) ? 0 : 1;
    } else {
        Ah = g_ph; Al = g_pl;
        Bh = g_wh + 12582912; Bl = g_wl + 12582912;
        dst = dst_ext;
        mode = 2;
    }
    const int cidx = sel - 1;

    extern __shared__ char smem[];
    const uint32_t sb = smem_u32(smem);
    const int tid = threadIdx.x;
    const int wid = tid >> 5, lid = tid & 31;
    const int wm = wid & 3, wn2 = wid >> 2;
    const int n0 = blockIdx.x * 64, m0 = blockIdx.y * 128;

    float acc1[2][4][4], acc2[2][4][4];
#pragma unroll
    for (int mt = 0; mt < 2; mt++)
#pragma unroll
        for (int nt = 0; nt < 4; nt++)
#pragma unroll
            for (int e = 0; e < 4; e++) { acc1[mt][nt][e] = 0.f; acc2[mt][nt][e] = 0.f; }

    const int sub = lid >> 3, lr = lid & 7;
    const uint32_t rowA = wm * 32 + (sub & 1) * 8 + lr;   // + mt*16
    const uint32_t rowB = wn2 * 32 + (sub & 1) * 8 + lr;  // + p*16
    const uint32_t kb   = (sub >> 1) * 16;                // byte offset (+8 halves)

    ld_stage(sb, Ah, Al, Bh, Bl, m0, n0, 0, tid);
    CP_COMMIT();

    for (int it = 0; it < 64; it++) {
        CP_WAIT0();
        __syncthreads();
        if (it + 1 < 64) {
            ld_stage(sb + ((it + 1) & 1) * STAGE_BYTES, Ah, Al, Bh, Bl,
                     m0, n0, (it + 1) * 32, tid);
            CP_COMMIT();
        }
        const uint32_t st = sb + (it & 1) * STAGE_BYTES;
#pragma unroll
        for (int ks = 0; ks < 2; ks++) {
            uint32_t ah[2][4], al[2][4], bhf[4][2], blf[4][2];
#pragma unroll
            for (int mt = 0; mt < 2; mt++) {
                uint32_t ra = (rowA + mt * 16) * 80 + kb + ks * 32;
                LDSM_X4(ah[mt], st + OFF_AH + ra);
                LDSM_X4(al[mt], st + OFF_AL + ra);
            }
#pragma unroll
            for (int p = 0; p < 2; p++) {
                uint32_t rb = (rowB + p * 16) * 80 + kb + ks * 32;
                uint32_t t[4];
                LDSM_X4(t, st + OFF_BH + rb);
                bhf[2 * p][0] = t[0]; bhf[2 * p][1] = t[2];
                bhf[2 * p + 1][0] = t[1]; bhf[2 * p + 1][1] = t[3];
                LDSM_X4(t, st + OFF_BL + rb);
                blf[2 * p][0] = t[0]; blf[2 * p][1] = t[2];
                blf[2 * p + 1][0] = t[1]; blf[2 * p + 1][1] = t[3];
            }
#pragma unroll
            for (int mt = 0; mt < 2; mt++)
#pragma unroll
                for (int nt = 0; nt < 4; nt++) {
                    MMA16816(acc1[mt][nt], ah[mt], bhf[nt]);
                    MMA16816(acc2[mt][nt], ah[mt], blf[nt]);
                    MMA16816(acc2[mt][nt], al[mt], bhf[nt]);
                }
        }
        __syncthreads();
    }

    const float INV = 4.8828125e-4f;          // 2^-11
    const float SCALE = 0.08838834764831845f; // 1/sqrt(128)
    const float TAU = 1e-3f;
    const int gid = lid >> 2, t4 = lid & 3;
#pragma unroll
    for (int mt = 0; mt < 2; mt++)
#pragma unroll
        for (int nt = 0; nt < 4; nt++) {
            int row = m0 + wm * 32 + mt * 16 + gid;
            int col = n0 + wn2 * 32 + nt * 8 + t4 * 2;
            float d0 = acc1[mt][nt][0] + acc2[mt][nt][0] * INV;
            float d1 = acc1[mt][nt][1] + acc2[mt][nt][1] * INV;
            float d2 = acc1[mt][nt][2] + acc2[mt][nt][2] * INV;
            float d3 = acc1[mt][nt][3] + acc2[mt][nt][3] * INV;
            if (mode == 0) { d0 *= SCALE; d1 *= SCALE; d2 *= SCALE; d3 *= SCALE; }
            else if (mode == 1) {
                unsigned base0 = (unsigned)(row * 2048 + col);
                unsigned base2 = base0 + 8 * 2048;
                if (fabsf(d0) < TAU) { int ix = atomicAdd(&g_cnt[cidx], 1); if (ix < FIX_CAP) g_cand[cidx][ix] = base0; }
                if (fabsf(d1) < TAU) { int ix = atomicAdd(&g_cnt[cidx], 1); if (ix < FIX_CAP) g_cand[cidx][ix] = base0 + 1; }
                if (fabsf(d2) < TAU) { int ix = atomicAdd(&g_cnt[cidx], 1); if (ix < FIX_CAP) g_cand[cidx][ix] = base2; }
                if (fabsf(d3) < TAU) { int ix = atomicAdd(&g_cnt[cidx], 1); if (ix < FIX_CAP) g_cand[cidx][ix] = base2 + 1; }
                d0 = (d0 >= 0.f) ? 1.f : -1.f; d1 = (d1 >= 0.f) ? 1.f : -1.f;
                d2 = (d2 >= 0.f) ? 1.f : -1.f; d3 = (d3 >= 0.f) ? 1.f : -1.f;
            }
            *reinterpret_cast<float2*>(dst + (size_t)row * 2048 + col) = make_float2(d0, d1);
            *reinterpret_cast<float2*>(dst + (size_t)(row + 8) * 2048 + col) = make_float2(d2, d3);
        }
}

// --------------------- exact-sign fixup, fp64 (warp per candidate) ----------
__global__ __launch_bounds__(256) void fixup_kernel(
    const float* __restrict__ x, const float* __restrict__ W, int which)
{
    int cnt = g_cnt[which];
    if (cnt > FIX_CAP) cnt = FIX_CAP;
    int wgid = (blockIdx.x * 256 + threadIdx.x) >> 5;
    int lane = threadIdx.x & 31;
    int nw = (gridDim.x * 256) >> 5;
    float* dst = which ? g_v : g_k;
    const unsigned* cand = g_cand[which];
    for (int i = wgid; i < cnt; i += nw) {
        unsigned pc = cand[i];
        int row = pc >> 11, col = pc & 2047;
        const float4* xr = reinterpret_cast<const float4*>(x + (size_t)row * 2048);
        const float4* wr = reinterpret_cast<const float4*>(W + (size_t)col * 2048);
        double s = 0.0;
        for (int j = lane; j < 512; j += 32) {
            float4 a = xr[j], b = wr[j];
            s += (double)a.x * b.x + (double)a.y * b.y
               + (double)a.z * b.z + (double)a.w * b.w;
        }
#pragma unroll
        for (int o = 16; o; o >>= 1) s += __shfl_xor_sync(0xFFFFFFFFu, s, o);
        if (lane == 0) dst[(size_t)row * 2048 + col] = (s >= 0.0) ? 1.f : -1.f;
    }
}

// ------------------ chunk kernels (unchanged from passing run) --------------
#define INNER_STEP(kk)                                                        \
    {                                                                         \
        float a[8], b[8];                                                     \
        *reinterpret_cast<float4*>(a)   = *reinterpret_cast<const float4*>(&As[kk][ty*8]);   \
        *reinterpret_cast<float4*>(a+4) = *reinterpret_cast<const float4*>(&As[kk][ty*8+4]); \
        *reinterpret_cast<float4*>(b)   = *reinterpret_cast<const float4*>(&Bs[kk][tx*8]);   \
        *reinterpret_cast<float4*>(b+4) = *reinterpret_cast<const float4*>(&Bs[kk][tx*8+4]); \
        _Pragma("unroll")                                                     \
        for (int u = 0; u < 8; u++)                                           \
            _Pragma("unroll")                                                 \
            for (int v = 0; v < 8; v++)                                       \
                acc[u][v] += a[u] * b[v];                                     \
    }

__global__ __launch_bounds__(256) void chunk_delta_kernel()
{
    const int c = blockIdx.x;
    const int bh = blockIdx.y;
    const int b = bh >> 4, h = bh & 15;
    const size_t base_row = (size_t)b * 4096 + (size_t)c * 128;
    const int col0 = h * 128;

    __shared__ float As[16][132];
    __shared__ float Bs[16][132];
    float acc[8][8];
#pragma unroll
    for (int u = 0; u < 8; u++)
#pragma unroll
        for (int v = 0; v < 8; v++) acc[u][v] = 0.f;

    const int tid = threadIdx.x;
    const int tx = tid & 15, ty = tid >> 4;

    for (int t0 = 0; t0 < 128; t0 += 16) {
#pragma unroll
        for (int r = 0; r < 2; r++) {
            int linear = r * 256 + tid;
            int kk = linear >> 5;
            int i4 = (linear & 31) << 2;
            *reinterpret_cast<float4*>(&As[kk][i4]) =
                *reinterpret_cast<const float4*>(g_k + (base_row + t0 + kk) * 2048 + col0 + i4);
            *reinterpret_cast<float4*>(&Bs[kk][i4]) =
                *reinterpret_cast<const float4*>(g_v + (base_row + t0 + kk) * 2048 + col0 + i4);
        }
        __syncthreads();
#pragma unroll
        for (int kk = 0; kk < 16; kk++) INNER_STEP(kk);
        __syncthreads();
    }

    float* dst = g_states + ((size_t)bh * 33 + c + 1) * 16384;
#pragma unroll
    for (int u = 0; u < 8; u++)
#pragma unroll
        for (int v = 0; v < 8; v++)
            dst[(ty * 8 + u) * 128 + tx * 8 + v] = acc[u][v];
}

__global__ __launch_bounds__(256) void prefix_state_kernel(float* __restrict__ out_state)
{
    int idx = blockIdx.x * 256 + threadIdx.x;
    int bh = idx >> 14;
    int rest = idx & 16383;
    size_t base = (size_t)bh * 33 * 16384 + rest;
    g_states[base] = 0.f;
    float run = 0.f;
#pragma unroll
    for (int c = 0; c < 32; c++) {
        size_t p = base + (size_t)(c + 1) * 16384;
        run += g_states[p];
        g_states[p] = run;
    }
    out_state[idx] = run;
}

__global__ __launch_bounds__(256) void chunk_scores_kernel()
{
    const int c = blockIdx.x;
    const int bh = blockIdx.y;
    const int b = bh >> 4, h = bh & 15;
    const size_t base_row = (size_t)b * 4096 + (size_t)c * 128;
    const int col0 = h * 128;

    __shared__ float As[16][132];
    __shared__ float Bs[16][132];
    float acc[8][8];
#pragma unroll
    for (int u = 0; u < 8; u++)
#pragma unroll
        for (int v = 0; v < 8; v++) acc[u][v] = 0.f;

    const int tid = threadIdx.x;
    const int tx = tid & 15, ty = tid >> 4;

    for (int k0 = 0; k0 < 128; k0 += 16) {
#pragma unroll
        for (int r = 0; r < 2; r++) {
            int linear = r * 256 + tid;
            int mm = linear >> 2;
            int kq = (linear & 3) << 2;
            float4 va = *reinterpret_cast<const float4*>(g_q + (base_row + mm) * 2048 + col0 + k0 + kq);
            As[kq + 0][mm] = va.x; As[kq + 1][mm] = va.y; As[kq + 2][mm] = va.z; As[kq + 3][mm] = va.w;
            float4 vb = *reinterpret_cast<const float4*>(g_k + (base_row + mm) * 2048 + col0 + k0 + kq);
            Bs[kq + 0][mm] = vb.x; Bs[kq + 1][mm] = vb.y; Bs[kq + 2][mm] = vb.z; Bs[kq + 3][mm] = vb.w;
        }
        __syncthreads();
#pragma unroll
        for (int kk = 0; kk < 16; kk++) INNER_STEP(kk);
        __syncthreads();
    }

    float* dst = g_scores + ((size_t)bh * 32 + c) * 16384;
#pragma unroll
    for (int u = 0; u < 8; u++) {
        int row = ty * 8 + u;
#pragma unroll
        for (int v = 0; v < 8; v++) {
            int col = tx * 8 + v;
            dst[row * 128 + col] = (col <= row) ? acc[u][v] : 0.f;
        }
    }
}

__global__ __launch_bounds__(256) void chunk_out_kernel()
{
    const int c = blockIdx.x;
    const int bh = blockIdx.y;
    const int b = bh >> 4, h = bh & 15;
    const size_t base_row = (size_t)b * 4096 + (size_t)c * 128;
    const int col0 = h * 128;

    __shared__ float As[16][132];
    __shared__ float Bs[16][132];
    float acc[8][8];
#pragma unroll
    for (int u = 0; u < 8; u++)
#pragma unroll
        for (int v = 0; v < 8; v++) acc[u][v] = 0.f;

    const int tid = threadIdx.x;
    const int tx = tid & 15, ty = tid >> 4;

    const float* sc = g_scores + ((size_t)bh * 32 + c) * 16384;

    for (int t0 = 0; t0 < 128; t0 += 16) {
#pragma unroll
        for (int r = 0; r < 2; r++) {
            int linear = r * 256 + tid;
            int mm = linear >> 2;
            int kq = (linear & 3) << 2;
            float4 va = *reinterpret_cast<const float4*>(sc + mm * 128 + t0 + kq);
            As[kq + 0][mm] = va.x; As[kq + 1][mm] = va.y; As[kq + 2][mm] = va.z; As[kq + 3][mm] = va.w;
            int kk = linear >> 5;
            int e4 = (linear & 31) << 2;
            *reinterpret_cast<float4*>(&Bs[kk][e4]) =
                *reinterpret_cast<const float4*>(g_v + (base_row + t0 + kk) * 2048 + col0 + e4);
        }
        __syncthreads();
#pragma unroll
        for (int kk = 0; kk < 16; kk++) INNER_STEP(kk);
        __syncthreads();
    }

    const float* st = g_states + ((size_t)bh * 33 + c) * 16384;
    for (int j0 = 0; j0 < 128; j0 += 16) {
#pragma unroll
        for (int r = 0; r < 2; r++) {
            int linear = r * 256 + tid;
            int mm = linear >> 2;
            int kq = (linear & 3) << 2;
            float4 va = *reinterpret_cast<const float4*>(g_q + (base_row + mm) * 2048 + col0 + j0 + kq);
            As[kq + 0][mm] = va.x; As[kq + 1][mm] = va.y; As[kq + 2][mm] = va.z; As[kq + 3][mm] = va.w;
            int kk = linear >> 5;
            int e4 = (linear & 31) << 2;
            *reinterpret_cast<float4*>(&Bs[kk][e4]) =
                *reinterpret_cast<const float4*>(st + (j0 + kk) * 128 + e4);
        }
        __syncthreads();
#pragma unroll
        for (int kk = 0; kk < 16; kk++) INNER_STEP(kk);
        __syncthreads();
    }

#pragma unroll
    for (int u = 0; u < 8; u++)
#pragma unroll
        for (int v = 0; v < 8; v++)
            g_pre[(base_row + ty * 8 + u) * 2048 + col0 + tx * 8 + v] = acc[u][v];
}

// ---------------------------------------------------------------------------
extern "C" void kernel_launch(void* const* d_in, const int* in_sizes, int n_in,
                              void* d_out, int out_size)
{
    const float* x  = (const float*)d_in[0];
    const float* Wq = (const float*)d_in[1];
    const float* Wk = (const float*)d_in[2];
    const float* Wv = (const float*)d_in[3];
    const float* Wo = (const float*)d_in[4];
    float* out = (float*)d_out;   // [33554432] out + [1048576] final_state

    cudaFuncSetAttribute(hgemm3_kernel, cudaFuncAttributeMaxDynamicSharedMemorySize, SMEM_HG);

    reset_cnt_kernel<<<1, 32>>>();

    // fp16 hi/lo splits
    split_h_kernel<<<2048, 256>>>(x,  0, 8388608);
    split_h_kernel<<<1024, 256>>>(Wq, 1, 1048576);
    split_h_kernel<<<1024, 256>>>(Wk, 2, 1048576);
    split_h_kernel<<<1024, 256>>>(Wv, 3, 1048576);
    split_h_kernel<<<1024, 256>>>(Wo, 4, 1048576);

    // projections on HMMA (3-term fp16, pipelined)
    hgemm3_kernel<<<dim3(32, 128), 256, SMEM_HG>>>(nullptr, 0);   // q
    hgemm3_kernel<<<dim3(32, 128), 256, SMEM_HG>>>(nullptr, 1);   // k
    hgemm3_kernel<<<dim3(32, 128), 256, SMEM_HG>>>(nullptr, 2);   // v

    // exact fp64 sign fixup for near-zero K/V projections
    fixup_kernel<<<1024, 256>>>(x, Wk, 0);
    fixup_kernel<<<1024, 256>>>(x, Wv, 1);

    // chunked recurrence (unchanged)
    chunk_delta_kernel<<<dim3(32, 64), 256>>>();
    prefix_state_kernel<<<4096, 256>>>(out + 33554432);
    chunk_scores_kernel<<<dim3(32, 64), 256>>>();
    chunk_out_kernel<<<dim3(32, 64), 256>>>();

    // output projection
    split_h_kernel<<<2048, 256>>>(nullptr, 5, 8388608);
    hgemm3_kernel<<<dim3(32, 128), 256, SMEM_HG>>>(out, 3);
}

// round 15
// speedup vs baseline: 1.7810x; 1.0308x over previous
#include <cuda_runtime.h>
#include <cuda_fp16.h>
#include <cstdint>

// ---------------------------------------------------------------------------
// BinaryAssociativeMemory on GB300 — round 15.
// R14 passed at 7293us; hgemm3 at ~30% tensor utilization, scheduling-bound.
// Changes (MMA order bit-identical -> rel_err unchanged):
//   1. 3-stage cp.async pipeline (wait_group 1), one __syncthreads per k-iter.
//   2. chunk_out splits its output to g_ph/g_pl inline (pre-split pass gone).
// ---------------------------------------------------------------------------

#define FIX_CAP 8388608

// ------------------------------- scratch ----------------------------------
__device__ float g_q[33554432];       // [16384, 2048]
__device__ float g_k[33554432];
__device__ float g_v[33554432];
__device__ float g_scores[33554432];  // [64*32][128][128]
__device__ float g_states[34603008];  // [64][33][128][128]
__device__ __half g_xh[33554432], g_xl[33554432];
__device__ __half g_ph[33554432], g_pl[33554432];
__device__ __half g_wh[16777216], g_wl[16777216];   // Wq|Wk|Wv|Wo
__device__ int g_cnt[2];
__device__ unsigned g_cand[2][FIX_CAP];

// --------------------------- asm helpers -----------------------------------
__device__ __forceinline__ uint32_t smem_u32(const void* p) {
    uint32_t a;
    asm("{ .reg .u64 t; cvta.to.shared.u64 t, %1; cvt.u32.u64 %0, t; }"
        : "=r"(a) : "l"(p));
    return a;
}

#define CP16(dst, src) \
    asm volatile("cp.async.cg.shared.global [%0], [%1], 16;" \
                 :: "r"(dst), "l"(src) : "memory")
#define CP_COMMIT() asm volatile("cp.async.commit_group;" ::: "memory")
#define CP_WAIT0()  asm volatile("cp.async.wait_group 0;" ::: "memory")
#define CP_WAIT1()  asm volatile("cp.async.wait_group 1;" ::: "memory")

#define LDSM_X4(r, a) \
    asm volatile("ldmatrix.sync.aligned.m8n8.x4.shared.b16 {%0,%1,%2,%3}, [%4];" \
                 : "=r"((r)[0]), "=r"((r)[1]), "=r"((r)[2]), "=r"((r)[3]) : "r"(a))

#define MMA16816(d, a, b) \
    asm volatile("mma.sync.aligned.m16n8k16.row.col.f32.f16.f16.f32 " \
                 "{%0,%1,%2,%3}, {%4,%5,%6,%7}, {%8,%9}, {%0,%1,%2,%3};" \
                 : "+f"((d)[0]), "+f"((d)[1]), "+f"((d)[2]), "+f"((d)[3]) \
                 : "r"((a)[0]), "r"((a)[1]), "r"((a)[2]), "r"((a)[3]), \
                   "r"((b)[0]), "r"((b)[1]))

// --------------------------- reset kernel -----------------------------------
__global__ void reset_cnt_kernel() {
    if (threadIdx.x < 2) g_cnt[threadIdx.x] = 0;
}

// --------------------------- fp16 split kernel ------------------------------
// hi = fp16(x); lo = fp16((x - hi) * 2048)
// sel: 0 -> x; 1..4 -> W (Wq,Wk,Wv,Wo)
__global__ __launch_bounds__(256) void split_h_kernel(
    const float* __restrict__ src_ext, int sel, int n4)
{
    const float* src = src_ext;
    __half* hi;
    __half* lo;
    if (sel == 0) { hi = g_xh; lo = g_xl; }
    else {
        size_t off = (size_t)(sel - 1) * 4194304;
        hi = g_wh + off; lo = g_wl + off;
    }

    int i = blockIdx.x * 256 + threadIdx.x;
    int stride = gridDim.x * 256;
    for (; i < n4; i += stride) {
        float4 v = reinterpret_cast<const float4*>(src)[i];
        __half h0 = __float2half_rn(v.x);
        __half h1 = __float2half_rn(v.y);
        __half h2 = __float2half_rn(v.z);
        __half h3 = __float2half_rn(v.w);
        __half l0 = __float2half_rn((v.x - __half2float(h0)) * 2048.0f);
        __half l1 = __float2half_rn((v.y - __half2float(h1)) * 2048.0f);
        __half l2 = __float2half_rn((v.z - __half2float(h2)) * 2048.0f);
        __half l3 = __float2half_rn((v.w - __half2float(h3)) * 2048.0f);
        __half2* hp = reinterpret_cast<__half2*>(hi + (size_t)i * 4);
        __half2* lp = reinterpret_cast<__half2*>(lo + (size_t)i * 4);
        hp[0] = __halves2half2(h0, h1); hp[1] = __halves2half2(h2, h3);
        lp[0] = __halves2half2(l0, l1); lp[1] = __halves2half2(l2, l3);
    }
}

// --------------------- fp16 3-term HMMA GEMM (3-stage pipeline) -------------
// C[16384,2048] = A @ B^T (TN). CTA 128x64x32, 8 warps, warp 32x32.
// sel: 0 -> q (*SCALE), 1 -> k (sign+cand), 2 -> v (sign+cand), 3 -> out
#define OFF_AH 0
#define OFF_AL 10240
#define OFF_BH 20480
#define OFF_BL 25600
#define STAGE_BYTES 30720
#define SMEM_HG (3 * STAGE_BYTES)

__device__ __forceinline__ void ld_stage(
    uint32_t base, const __half* __restrict__ Ah, const __half* __restrict__ Al,
    const __half* __restrict__ Bh, const __half* __restrict__ Bl,
    int m0, int n0, int k0, int tid)
{
#pragma unroll
    for (int i = 0; i < 2; i++) {                       // A: 128 rows x 4x16B
        int ch = i * 256 + tid;
        int r = ch >> 2, c = ch & 3;
        uint32_t d = base + OFF_AH + r * 80 + c * 16;
        CP16(d, Ah + (size_t)(m0 + r) * 2048 + k0 + c * 8);
        d = base + OFF_AL + r * 80 + c * 16;
        CP16(d, Al + (size_t)(m0 + r) * 2048 + k0 + c * 8);
    }
    {                                                   // B: 64 rows x 4x16B
        int r = tid >> 2, c = tid & 3;
        uint32_t d = base + OFF_BH + r * 80 + c * 16;
        CP16(d, Bh + (size_t)(n0 + r) * 2048 + k0 + c * 8);
        d = base + OFF_BL + r * 80 + c * 16;
        CP16(d, Bl + (size_t)(n0 + r) * 2048 + k0 + c * 8);
    }
}

__global__ __launch_bounds__(256) void hgemm3_kernel(float* __restrict__ dst_ext, int sel)
{
    const __half* Ah;
    const __half* Al;
    const __half* Bh;
    const __half* Bl;
    float* dst;
    int mode;
    if (sel < 3) {
        Ah = g_xh; Al = g_xl;
        size_t off = (size_t)sel * 4194304;
        Bh = g_wh + off; Bl = g_wl + off;
        dst = (sel == 0) ? g_q : ((sel == 1) ? g_k : g_v);
        mode = (sel == 0) ? 0 : 1;
    } else {
        Ah = g_ph; Al = g_pl;
        Bh = g_wh + 12582912; Bl = g_wl + 12582912;
        dst = dst_ext;
        mode = 2;
    }
    const int cidx = sel - 1;

    extern __shared__ char smem[];
    const uint32_t sb = smem_u32(smem);
    const int tid = threadIdx.x;
    const int wid = tid >> 5, lid = tid & 31;
    const int wm = wid & 3, wn2 = wid >> 2;
    const int n0 = blockIdx.x * 64, m0 = blockIdx.y * 128;

    float acc1[2][4][4], acc2[2][4][4];
#pragma unroll
    for (int mt = 0; mt < 2; mt++)
#pragma unroll
        for (int nt = 0; nt < 4; nt++)
#pragma unroll
            for (int e = 0; e < 4; e++) { acc1[mt][nt][e] = 0.f; acc2[mt][nt][e] = 0.f; }

    const int sub = lid >> 3, lr = lid & 7;
    const uint32_t rowA = wm * 32 + (sub & 1) * 8 + lr;
    const uint32_t rowB = wn2 * 32 + (sub & 1) * 8 + lr;
    const uint32_t kb   = (sub >> 1) * 16;

    // prologue: stages 0, 1
    ld_stage(sb + 0 * STAGE_BYTES, Ah, Al, Bh, Bl, m0, n0, 0, tid);
    CP_COMMIT();
    ld_stage(sb + 1 * STAGE_BYTES, Ah, Al, Bh, Bl, m0, n0, 32, tid);
    CP_COMMIT();

    int buf = 0;
    for (int it = 0; it < 64; it++) {
        if (it < 62) CP_WAIT1(); else CP_WAIT0();
        __syncthreads();
        if (it + 2 < 64) {
            int nb = buf + 2; if (nb >= 3) nb -= 3;
            ld_stage(sb + nb * STAGE_BYTES, Ah, Al, Bh, Bl, m0, n0, (it + 2) * 32, tid);
            CP_COMMIT();
        }
        const uint32_t st = sb + buf * STAGE_BYTES;
#pragma unroll
        for (int ks = 0; ks < 2; ks++) {
            uint32_t ah[2][4], al[2][4], bhf[4][2], blf[4][2];
#pragma unroll
            for (int mt = 0; mt < 2; mt++) {
                uint32_t ra = (rowA + mt * 16) * 80 + kb + ks * 32;
                LDSM_X4(ah[mt], st + OFF_AH + ra);
                LDSM_X4(al[mt], st + OFF_AL + ra);
            }
#pragma unroll
            for (int p = 0; p < 2; p++) {
                uint32_t rb = (rowB + p * 16) * 80 + kb + ks * 32;
                uint32_t t[4];
                LDSM_X4(t, st + OFF_BH + rb);
                bhf[2 * p][0] = t[0]; bhf[2 * p][1] = t[2];
                bhf[2 * p + 1][0] = t[1]; bhf[2 * p + 1][1] = t[3];
                LDSM_X4(t, st + OFF_BL + rb);
                blf[2 * p][0] = t[0]; blf[2 * p][1] = t[2];
                blf[2 * p + 1][0] = t[1]; blf[2 * p + 1][1] = t[3];
            }
#pragma unroll
            for (int mt = 0; mt < 2; mt++)
#pragma unroll
                for (int nt = 0; nt < 4; nt++) {
                    MMA16816(acc1[mt][nt], ah[mt], bhf[nt]);
                    MMA16816(acc2[mt][nt], ah[mt], blf[nt]);
                    MMA16816(acc2[mt][nt], al[mt], bhf[nt]);
                }
        }
        if (++buf == 3) buf = 0;
    }

    const float INV = 4.8828125e-4f;          // 2^-11
    const float SCALE = 0.08838834764831845f; // 1/sqrt(128)
    const float TAU = 1e-3f;
    const int gid = lid >> 2, t4 = lid & 3;
#pragma unroll
    for (int mt = 0; mt < 2; mt++)
#pragma unroll
        for (int nt = 0; nt < 4; nt++) {
            int row = m0 + wm * 32 + mt * 16 + gid;
            int col = n0 + wn2 * 32 + nt * 8 + t4 * 2;
            float d0 = acc1[mt][nt][0] + acc2[mt][nt][0] * INV;
            float d1 = acc1[mt][nt][1] + acc2[mt][nt][1] * INV;
            float d2 = acc1[mt][nt][2] + acc2[mt][nt][2] * INV;
            float d3 = acc1[mt][nt][3] + acc2[mt][nt][3] * INV;
            if (mode == 0) { d0 *= SCALE; d1 *= SCALE; d2 *= SCALE; d3 *= SCALE; }
            else if (mode == 1) {
                unsigned base0 = (unsigned)(row * 2048 + col);
                unsigned base2 = base0 + 8 * 2048;
                if (fabsf(d0) < TAU) { int ix = atomicAdd(&g_cnt[cidx], 1); if (ix < FIX_CAP) g_cand[cidx][ix] = base0; }
                if (fabsf(d1) < TAU) { int ix = atomicAdd(&g_cnt[cidx], 1); if (ix < FIX_CAP) g_cand[cidx][ix] = base0 + 1; }
                if (fabsf(d2) < TAU) { int ix = atomicAdd(&g_cnt[cidx], 1); if (ix < FIX_CAP) g_cand[cidx][ix] = base2; }
                if (fabsf(d3) < TAU) { int ix = atomicAdd(&g_cnt[cidx], 1); if (ix < FIX_CAP) g_cand[cidx][ix] = base2 + 1; }
                d0 = (d0 >= 0.f) ? 1.f : -1.f; d1 = (d1 >= 0.f) ? 1.f : -1.f;
                d2 = (d2 >= 0.f) ? 1.f : -1.f; d3 = (d3 >= 0.f) ? 1.f : -1.f;
            }
            *reinterpret_cast<float2*>(dst + (size_t)row * 2048 + col) = make_float2(d0, d1);
            *reinterpret_cast<float2*>(dst + (size_t)(row + 8) * 2048 + col) = make_float2(d2, d3);
        }
}

// --------------------- exact-sign fixup, fp64 (warp per candidate) ----------
__global__ __launch_bounds__(256) void fixup_kernel(
    const float* __restrict__ x, const float* __restrict__ W, int which)
{
    int cnt = g_cnt[which];
    if (cnt > FIX_CAP) cnt = FIX_CAP;
    int wgid = (blockIdx.x * 256 + threadIdx.x) >> 5;
    int lane = threadIdx.x & 31;
    int nw = (gridDim.x * 256) >> 5;
    float* dst = which ? g_v : g_k;
    const unsigned* cand = g_cand[which];
    for (int i = wgid; i < cnt; i += nw) {
        unsigned pc = cand[i];
        int row = pc >> 11, col = pc & 2047;
        const float4* xr = reinterpret_cast<const float4*>(x + (size_t)row * 2048);
        const float4* wr = reinterpret_cast<const float4*>(W + (size_t)col * 2048);
        double s = 0.0;
        for (int j = lane; j < 512; j += 32) {
            float4 a = xr[j], b = wr[j];
            s += (double)a.x * b.x + (double)a.y * b.y
               + (double)a.z * b.z + (double)a.w * b.w;
        }
#pragma unroll
        for (int o = 16; o; o >>= 1) s += __shfl_xor_sync(0xFFFFFFFFu, s, o);
        if (lane == 0) dst[(size_t)row * 2048 + col] = (s >= 0.0) ? 1.f : -1.f;
    }
}

// ------------------ chunk kernels (FFMA, known-passing) ---------------------
#define INNER_STEP(kk)                                                        \
    {                                                                         \
        float a[8], b[8];                                                     \
        *reinterpret_cast<float4*>(a)   = *reinterpret_cast<const float4*>(&As[kk][ty*8]);   \
        *reinterpret_cast<float4*>(a+4) = *reinterpret_cast<const float4*>(&As[kk][ty*8+4]); \
        *reinterpret_cast<float4*>(b)   = *reinterpret_cast<const float4*>(&Bs[kk][tx*8]);   \
        *reinterpret_cast<float4*>(b+4) = *reinterpret_cast<const float4*>(&Bs[kk][tx*8+4]); \
        _Pragma("unroll")                                                     \
        for (int u = 0; u < 8; u++)                                           \
            _Pragma("unroll")                                                 \
            for (int v = 0; v < 8; v++)                                       \
                acc[u][v] += a[u] * b[v];                                     \
    }

__global__ __launch_bounds__(256) void chunk_delta_kernel()
{
    const int c = blockIdx.x;
    const int bh = blockIdx.y;
    const int b = bh >> 4, h = bh & 15;
    const size_t base_row = (size_t)b * 4096 + (size_t)c * 128;
    const int col0 = h * 128;

    __shared__ float As[16][132];
    __shared__ float Bs[16][132];
    float acc[8][8];
#pragma unroll
    for (int u = 0; u < 8; u++)
#pragma unroll
        for (int v = 0; v < 8; v++) acc[u][v] = 0.f;

    const int tid = threadIdx.x;
    const int tx = tid & 15, ty = tid >> 4;

    for (int t0 = 0; t0 < 128; t0 += 16) {
#pragma unroll
        for (int r = 0; r < 2; r++) {
            int linear = r * 256 + tid;
            int kk = linear >> 5;
            int i4 = (linear & 31) << 2;
            *reinterpret_cast<float4*>(&As[kk][i4]) =
                *reinterpret_cast<const float4*>(g_k + (base_row + t0 + kk) * 2048 + col0 + i4);
            *reinterpret_cast<float4*>(&Bs[kk][i4]) =
                *reinterpret_cast<const float4*>(g_v + (base_row + t0 + kk) * 2048 + col0 + i4);
        }
        __syncthreads();
#pragma unroll
        for (int kk = 0; kk < 16; kk++) INNER_STEP(kk);
        __syncthreads();
    }

    float* dst = g_states + ((size_t)bh * 33 + c + 1) * 16384;
#pragma unroll
    for (int u = 0; u < 8; u++)
#pragma unroll
        for (int v = 0; v < 8; v++)
            dst[(ty * 8 + u) * 128 + tx * 8 + v] = acc[u][v];
}

__global__ __launch_bounds__(256) void prefix_state_kernel(float* __restrict__ out_state)
{
    int idx = blockIdx.x * 256 + threadIdx.x;
    int bh = idx >> 14;
    int rest = idx & 16383;
    size_t base = (size_t)bh * 33 * 16384 + rest;
    g_states[base] = 0.f;
    float run = 0.f;
#pragma unroll
    for (int c = 0; c < 32; c++) {
        size_t p = base + (size_t)(c + 1) * 16384;
        run += g_states[p];
        g_states[p] = run;
    }
    out_state[idx] = run;
}

__global__ __launch_bounds__(256) void chunk_scores_kernel()
{
    const int c = blockIdx.x;
    const int bh = blockIdx.y;
    const int b = bh >> 4, h = bh & 15;
    const size_t base_row = (size_t)b * 4096 + (size_t)c * 128;
    const int col0 = h * 128;

    __shared__ float As[16][132];
    __shared__ float Bs[16][132];
    float acc[8][8];
#pragma unroll
    for (int u = 0; u < 8; u++)
#pragma unroll
        for (int v = 0; v < 8; v++) acc[u][v] = 0.f;

    const int tid = threadIdx.x;
    const int tx = tid & 15, ty = tid >> 4;

    for (int k0 = 0; k0 < 128; k0 += 16) {
#pragma unroll
        for (int r = 0; r < 2; r++) {
            int linear = r * 256 + tid;
            int mm = linear >> 2;
            int kq = (linear & 3) << 2;
            float4 va = *reinterpret_cast<const float4*>(g_q + (base_row + mm) * 2048 + col0 + k0 + kq);
            As[kq + 0][mm] = va.x; As[kq + 1][mm] = va.y; As[kq + 2][mm] = va.z; As[kq + 3][mm] = va.w;
            float4 vb = *reinterpret_cast<const float4*>(g_k + (base_row + mm) * 2048 + col0 + k0 + kq);
            Bs[kq + 0][mm] = vb.x; Bs[kq + 1][mm] = vb.y; Bs[kq + 2][mm] = vb.z; Bs[kq + 3][mm] = vb.w;
        }
        __syncthreads();
#pragma unroll
        for (int kk = 0; kk < 16; kk++) INNER_STEP(kk);
        __syncthreads();
    }

    float* dst = g_scores + ((size_t)bh * 32 + c) * 16384;
#pragma unroll
    for (int u = 0; u < 8; u++) {
        int row = ty * 8 + u;
#pragma unroll
        for (int v = 0; v < 8; v++) {
            int col = tx * 8 + v;
            dst[row * 128 + col] = (col <= row) ? acc[u][v] : 0.f;
        }
    }
}

__global__ __launch_bounds__(256) void chunk_out_kernel()
{
    const int c = blockIdx.x;
    const int bh = blockIdx.y;
    const int b = bh >> 4, h = bh & 15;
    const size_t base_row = (size_t)b * 4096 + (size_t)c * 128;
    const int col0 = h * 128;

    __shared__ float As[16][132];
    __shared__ float Bs[16][132];
    float acc[8][8];
#pragma unroll
    for (int u = 0; u < 8; u++)
#pragma unroll
        for (int v = 0; v < 8; v++) acc[u][v] = 0.f;

    const int tid = threadIdx.x;
    const int tx = tid & 15, ty = tid >> 4;

    const float* sc = g_scores + ((size_t)bh * 32 + c) * 16384;

    for (int t0 = 0; t0 < 128; t0 += 16) {
#pragma unroll
        for (int r = 0; r < 2; r++) {
            int linear = r * 256 + tid;
            int mm = linear >> 2;
            int kq = (linear & 3) << 2;
            float4 va = *reinterpret_cast<const float4*>(sc + mm * 128 + t0 + kq);
            As[kq + 0][mm] = va.x; As[kq + 1][mm] = va.y; As[kq + 2][mm] = va.z; As[kq + 3][mm] = va.w;
            int kk = linear >> 5;
            int e4 = (linear & 31) << 2;
            *reinterpret_cast<float4*>(&Bs[kk][e4]) =
                *reinterpret_cast<const float4*>(g_v + (base_row + t0 + kk) * 2048 + col0 + e4);
        }
        __syncthreads();
#pragma unroll
        for (int kk = 0; kk < 16; kk++) INNER_STEP(kk);
        __syncthreads();
    }

    const float* st = g_states + ((size_t)bh * 33 + c) * 16384;
    for (int j0 = 0; j0 < 128; j0 += 16) {
#pragma unroll
        for (int r = 0; r < 2; r++) {
            int linear = r * 256 + tid;
            int mm = linear >> 2;
            int kq = (linear & 3) << 2;
            float4 va = *reinterpret_cast<const float4*>(g_q + (base_row + mm) * 2048 + col0 + j0 + kq);
            As[kq + 0][mm] = va.x; As[kq + 1][mm] = va.y; As[kq + 2][mm] = va.z; As[kq + 3][mm] = va.w;
            int kk = linear >> 5;
            int e4 = (linear & 31) << 2;
            *reinterpret_cast<float4*>(&Bs[kk][e4]) =
                *reinterpret_cast<const float4*>(st + (j0 + kk) * 128 + e4);
        }
        __syncthreads();
#pragma unroll
        for (int kk = 0; kk < 16; kk++) INNER_STEP(kk);
        __syncthreads();
    }

    // epilogue: split to fp16 hi/lo directly (same math as split_h_kernel)
#pragma unroll
    for (int u = 0; u < 8; u++) {
        size_t rowoff = (base_row + ty * 8 + u) * 2048 + col0 + tx * 8;
#pragma unroll
        for (int v2 = 0; v2 < 4; v2++) {
            float f0 = acc[u][v2 * 2], f1 = acc[u][v2 * 2 + 1];
            __half h0 = __float2half_rn(f0);
            __half h1 = __float2half_rn(f1);
            __half l0 = __float2half_rn((f0 - __half2float(h0)) * 2048.0f);
            __half l1 = __float2half_rn((f1 - __half2float(h1)) * 2048.0f);
            *reinterpret_cast<__half2*>(g_ph + rowoff + v2 * 2) = __halves2half2(h0, h1);
            *reinterpret_cast<__half2*>(g_pl + rowoff + v2 * 2) = __halves2half2(l0, l1);
        }
    }
}

// ---------------------------------------------------------------------------
extern "C" void kernel_launch(void* const* d_in, const int* in_sizes, int n_in,
                              void* d_out, int out_size)
{
    const float* x  = (const float*)d_in[0];
    const float* Wq = (const float*)d_in[1];
    const float* Wk = (const float*)d_in[2];
    const float* Wv = (const float*)d_in[3];
    const float* Wo = (const float*)d_in[4];
    float* out = (float*)d_out;   // [33554432] out + [1048576] final_state

    cudaFuncSetAttribute(hgemm3_kernel, cudaFuncAttributeMaxDynamicSharedMemorySize, SMEM_HG);

    reset_cnt_kernel<<<1, 32>>>();

    // fp16 hi/lo splits
    split_h_kernel<<<2048, 256>>>(x,  0, 8388608);
    split_h_kernel<<<1024, 256>>>(Wq, 1, 1048576);
    split_h_kernel<<<1024, 256>>>(Wk, 2, 1048576);
    split_h_kernel<<<1024, 256>>>(Wv, 3, 1048576);
    split_h_kernel<<<1024, 256>>>(Wo, 4, 1048576);

    // projections on HMMA (3-term fp16, 3-stage pipeline)
    hgemm3_kernel<<<dim3(32, 128), 256, SMEM_HG>>>(nullptr, 0);   // q
    hgemm3_kernel<<<dim3(32, 128), 256, SMEM_HG>>>(nullptr, 1);   // k
    hgemm3_kernel<<<dim3(32, 128), 256, SMEM_HG>>>(nullptr, 2);   // v

    // exact fp64 sign fixup for near-zero K/V projections
    fixup_kernel<<<1024, 256>>>(x, Wk, 0);
    fixup_kernel<<<1024, 256>>>(x, Wv, 1);

    // chunked recurrence (chunk_out now emits pre-split fp16 hi/lo)
    chunk_delta_kernel<<<dim3(32, 64), 256>>>();
    prefix_state_kernel<<<4096, 256>>>(out + 33554432);
    chunk_scores_kernel<<<dim3(32, 64), 256>>>();
    chunk_out_kernel<<<dim3(32, 64), 256>>>();

    // output projection
    hgemm3_kernel<<<dim3(32, 128), 256, SMEM_HG>>>(out, 3);
}